// round 9
// baseline (speedup 1.0000x reference)
#include <cuda_runtime.h>

// ---------------------------------------------------------------------------
// Elman RNN (relu), B=64, T=512, I=64, H=1024, O=64
// out = [ hidden_list (B,T,H) | output_list (B,T,O) | h_last (1,B,H) ]
// ---------------------------------------------------------------------------

#define B_   64
#define T_   512
#define I_   64
#define H_   1024
#define O_   64

#define HID_OFF  0
#define OUT_OFF  (B_ * T_ * H_)              // 33554432
#define HL_OFF   (OUT_OFF + B_ * T_ * O_)    // 35651584

#define NBLK 128        // persistent blocks (1/SM)
#define TB   256        // 2 warps / SMSP

// SMEM layout (floats): 32 K-chunks of 32 floats, each padded to 34
#define CH    34
#define HRow  1088      // 32 * 34

// scratch: h double buffer + per-(group,block) flags (128B stride)
__device__ __align__(16) float g_hbuf[2][B_ * H_];
__device__ unsigned g_flag[4][32][32];

typedef unsigned long long ull;

__device__ __forceinline__ ull f2fma(ull a, ull b, ull c) {
    ull d;
    asm("fma.rn.f32x2 %0, %1, %2, %3;" : "=l"(d) : "l"(a), "l"(b), "l"(c));
    return d;
}
__device__ __forceinline__ float pairsum(ull a) {
    float lo = __uint_as_float((unsigned)(a & 0xffffffffull));
    float hi = __uint_as_float((unsigned)(a >> 32));
    return lo + hi;
}
__device__ __forceinline__ unsigned ld_acq(unsigned* p) {
    unsigned v;
    asm volatile("ld.acquire.gpu.u32 %0, [%1];" : "=r"(v) : "l"(p) : "memory");
    return v;
}
__device__ __forceinline__ void st_rel(unsigned* p, unsigned v) {
    asm volatile("st.release.gpu.u32 [%0], %1;" :: "l"(p), "r"(v) : "memory");
}

// ---------------------------------------------------------------------------
__global__ void reset_flags() {
    ((unsigned*)g_flag)[blockIdx.x * blockDim.x + threadIdx.x] = 0;
}

// ---------------------------------------------------------------------------
// Kernel A: xw[bt][h] = x[bt]·W_ih[h] + b_ih[h] + b_hh[h]  -> hidden region
// ---------------------------------------------------------------------------
__global__ void __launch_bounds__(256) xw_kernel(
    const float* __restrict__ x, const float* __restrict__ Wih,
    const float* __restrict__ bih, const float* __restrict__ bhh,
    float* __restrict__ hid_out)
{
    __shared__ float xs[64 * 65];
    __shared__ float ws[64 * 65];

    const int tid = threadIdx.x;
    const int hb  = blockIdx.x * 64;
    const int btb = blockIdx.y * 64;

    #pragma unroll
    for (int i = tid; i < 64 * 64; i += 256) {
        int r = i >> 6, c = i & 63;
        xs[r * 65 + c] = x[(btb + r) * 64 + c];
        ws[r * 65 + c] = Wih[(hb + r) * 64 + c];
    }
    __syncthreads();

    const int tx = tid & 15, ty = tid >> 4;
    float acc[4][4] = {};

    #pragma unroll 8
    for (int k = 0; k < 64; ++k) {
        float a0 = xs[(ty     ) * 65 + k];
        float a1 = xs[(ty + 16) * 65 + k];
        float a2 = xs[(ty + 32) * 65 + k];
        float a3 = xs[(ty + 48) * 65 + k];
        float b0 = ws[(tx     ) * 65 + k];
        float b1 = ws[(tx + 16) * 65 + k];
        float b2 = ws[(tx + 32) * 65 + k];
        float b3 = ws[(tx + 48) * 65 + k];
        acc[0][0] += a0 * b0; acc[0][1] += a0 * b1; acc[0][2] += a0 * b2; acc[0][3] += a0 * b3;
        acc[1][0] += a1 * b0; acc[1][1] += a1 * b1; acc[1][2] += a1 * b2; acc[1][3] += a1 * b3;
        acc[2][0] += a2 * b0; acc[2][1] += a2 * b1; acc[2][2] += a2 * b2; acc[2][3] += a2 * b3;
        acc[3][0] += a3 * b0; acc[3][1] += a3 * b1; acc[3][2] += a3 * b2; acc[3][3] += a3 * b3;
    }

    #pragma unroll
    for (int j = 0; j < 4; ++j) {
        int h = hb + tx + 16 * j;
        float bb = bih[h] + bhh[h];
        #pragma unroll
        for (int i = 0; i < 4; ++i) {
            int bt = btb + ty + 16 * i;
            hid_out[bt * H_ + h] = acc[i][j] + bb;
        }
    }
}

// ---------------------------------------------------------------------------
// Kernel B: persistent recurrence with per-producer incremental staging.
// 128 blocks = 4 batch-groups(16 batches) x 32 col-groups(32 cols).
// Warp p (0..7) owns producers {p, p+8, p+16, p+24}: polls each flag and
// stages that producer's 32-col h chunk as soon as it is ready (straggler
// wait overlaps staging of ready chunks). Then full-block sync -> 8x8 f2fma
// tile (kc = lane) -> butterfly shuffle reduction -> relu epilogue ->
// __syncthreads -> warp0 releases own flag.
// ---------------------------------------------------------------------------
__global__ void __launch_bounds__(TB, 1) rnn_recur(
    const float* __restrict__ hid_in,
    const float* __restrict__ Whh,
    float* __restrict__ out)
{
    extern __shared__ float sm[];
    float* wsm = sm;                 // 32 rows x HRow  (~136 KB)
    float* hsm = sm + 32 * HRow;     // 16 rows x HRow  (~68 KB)

    const int tid = threadIdx.x;
    const int bi  = blockIdx.x >> 5;
    const int ci  = blockIdx.x & 31;
    const int b0  = bi * 16;
    const int c0  = ci * 32;

    const int lane = tid & 31;
    const int kc   = lane;             // K-chunk (lane-spanning)
    const int p    = tid >> 5;         // warp id / warp-uniform tile position
    const int pm   = p & 1;
    const int pn   = p >> 1;

    // ---- stage W_hh slice once: rows c0..c0+31, chunked layout ----
    const float2* W2 = (const float2*)Whh;
    #pragma unroll 4
    for (int i = tid; i < 32 * 512; i += TB) {
        int r = i >> 9, q = i & 511;
        *(float2*)&wsm[r * HRow + (q >> 4) * CH + (q & 15) * 2] =
            __ldg(&W2[(c0 + r) * 512 + q]);
    }

    const float* hb_ = hsm + pm * 8 * HRow + kc * CH;
    const float* wb_ = wsm + pn * 8 * HRow + kc * CH;

    float* hid_out = out + HID_OFF;
    float* hlast   = out + HL_OFF;

    // epilogue mapping (post-shuffle): lane holds outputs 2*lane, 2*lane+1 of
    // the warp's 64 = (batch pm*8 + (lane>>2), cols pn*8 + 2*(lane&3) + {0,1})
    const int gb = b0 + pm * 8 + (lane >> 2);
    const int gc = c0 + pn * 8 + 2 * (lane & 3);

    // staging mapping: float2 slot m (16 slots tile 128B per 16-lane phase),
    // rows split by half-warp -> conflict-free STS.64, coalesced LDG.64
    const int m_  = 2 * (lane & 7) + ((lane >> 3) & 1);   // 0..15
    const int rs_ = (lane >> 4) * 8;                       // 0 or 8

    #pragma unroll 1
    for (int s = 0; s < T_; ++s) {
        // prefetch xw for this thread's two outputs (own location, safe early)
        float2 xw = *(const float2*)&hid_out[((size_t)gb * T_ + s) * H_ + gc];

        // ---- per-producer poll + incremental chunk staging ----
        const float2* hsrc2 = (s == 0) ? (const float2*)hid_in
                                       : (const float2*)g_hbuf[(s - 1) & 1];
        #pragma unroll
        for (int jj = 0; jj < 4; ++jj) {
            const int j = p + jj * 8;          // producer col-group
            if (s > 0) {
                while ((int)(ld_acq(&g_flag[bi][j][0]) - (unsigned)s) < 0) { }
            }
            // stage chunk j: h[:, j*32..j*32+31] (16 rows x 16 float2)
            #pragma unroll
            for (int rr = 0; rr < 8; ++rr) {
                int row = rs_ + rr;
                float2 v = __ldcg(&hsrc2[(b0 + row) * 512 + j * 16 + m_]);
                *(float2*)&hsm[row * HRow + j * CH + 2 * m_] = v;
            }
        }
        __syncthreads();

        // ---- 8x8 tile over private K-chunk of 32 ----
        ull acc[64];
        #pragma unroll
        for (int i = 0; i < 64; ++i) acc[i] = 0ull;

        #pragma unroll
        for (int k2 = 0; k2 < 16; ++k2) {
            ull hv[8];
            #pragma unroll
            for (int i = 0; i < 8; ++i)
                hv[i] = *(const ull*)(hb_ + i * HRow + k2 * 2);
            ull wv[4];
            #pragma unroll
            for (int j = 0; j < 4; ++j)
                wv[j] = *(const ull*)(wb_ + j * HRow + k2 * 2);
            #pragma unroll
            for (int i = 0; i < 8; ++i)
                #pragma unroll
                for (int j = 0; j < 4; ++j)
                    acc[i * 8 + j] = f2fma(hv[i], wv[j], acc[i * 8 + j]);
            #pragma unroll
            for (int j = 0; j < 4; ++j)
                wv[j] = *(const ull*)(wb_ + (j + 4) * HRow + k2 * 2);
            #pragma unroll
            for (int i = 0; i < 8; ++i)
                #pragma unroll
                for (int j = 0; j < 4; ++j)
                    acc[i * 8 + j + 4] = f2fma(hv[i], wv[j], acc[i * 8 + j + 4]);
        }

        // ---- pairsum then 5-round butterfly shuffle reduction ----
        float vals[64];
        #pragma unroll
        for (int v = 0; v < 64; ++v) vals[v] = pairsum(acc[v]);

        #pragma unroll
        for (int mm = 16, cnt = 32; mm >= 1; mm >>= 1, cnt >>= 1) {
            bool up = (lane & mm) != 0;
            #pragma unroll
            for (int i = 0; i < 32; ++i) {
                if (i >= cnt) break;
                float send = up ? vals[i] : vals[i + cnt];
                float keep = up ? vals[i + cnt] : vals[i];
                float recv = __shfl_xor_sync(0xffffffffu, send, mm);
                vals[i] = keep + recv;
            }
        }
        // lane now holds vals[0], vals[1] = outputs 2*lane, 2*lane+1

        float2 rr2;
        rr2.x = fmaxf(xw.x + vals[0], 0.0f);
        rr2.y = fmaxf(xw.y + vals[1], 0.0f);

        *(float2*)&g_hbuf[s & 1][gb * H_ + gc] = rr2;
        *(float2*)&hid_out[((size_t)gb * T_ + s) * H_ + gc] = rr2;
        if (s == T_ - 1)
            *(float2*)&hlast[gb * H_ + gc] = rr2;

        // ---- full rendezvous, then warp 0 releases own flag ----
        if (s != T_ - 1) {
            __syncthreads();
            if (tid == 0)
                st_rel(&g_flag[bi][ci][0], (unsigned)(s + 1));
        }
    }
}

// ---------------------------------------------------------------------------
// Kernel C: output_list[bt][o] = hid[bt]·W_out[o] + b_out[o]   (f32x2)
// ---------------------------------------------------------------------------
__global__ void __launch_bounds__(256) out_kernel(
    const float* __restrict__ hid, const float* __restrict__ Wout,
    const float* __restrict__ bout, float* __restrict__ outp)
{
    __shared__ float hs[64 * 34];
    __shared__ float ws2[64 * 34];

    const int tid = threadIdx.x;
    const int btb = blockIdx.x * 64;
    const int tx = tid & 15, ty = tid >> 4;

    const float2* hid2  = (const float2*)hid;
    const float2* wout2 = (const float2*)Wout;

    ull acc[4][4];
    #pragma unroll
    for (int i = 0; i < 4; ++i)
        #pragma unroll
        for (int j = 0; j < 4; ++j) acc[i][j] = 0ull;

    for (int kcb = 0; kcb < 512; kcb += 16) {
        #pragma unroll
        for (int i = tid; i < 64 * 16; i += 256) {
            int rr = i >> 4, q = i & 15;
            *(float2*)&hs[rr * 34 + q * 2]  = hid2[(btb + rr) * 512 + kcb + q];
            *(float2*)&ws2[rr * 34 + q * 2] = wout2[rr * 512 + kcb + q];
        }
        __syncthreads();

        #pragma unroll
        for (int k2 = 0; k2 < 16; ++k2) {
            ull a[4], b[4];
            #pragma unroll
            for (int i = 0; i < 4; ++i)
                a[i] = *(const ull*)&hs[(ty + 16 * i) * 34 + k2 * 2];
            #pragma unroll
            for (int j = 0; j < 4; ++j)
                b[j] = *(const ull*)&ws2[(tx + 16 * j) * 34 + k2 * 2];
            #pragma unroll
            for (int i = 0; i < 4; ++i)
                #pragma unroll
                for (int j = 0; j < 4; ++j)
                    acc[i][j] = f2fma(a[i], b[j], acc[i][j]);
        }
        __syncthreads();
    }

    #pragma unroll
    for (int j = 0; j < 4; ++j) {
        int o = tx + 16 * j;
        float bb = bout[o];
        #pragma unroll
        for (int i = 0; i < 4; ++i)
            outp[(btb + ty + 16 * i) * O_ + o] = pairsum(acc[i][j]) + bb;
    }
}

// ---------------------------------------------------------------------------
extern "C" void kernel_launch(void* const* d_in, const int* in_sizes, int n_in,
                              void* d_out, int out_size) {
    const float* x      = (const float*)d_in[0];
    const float* hidden = (const float*)d_in[1];
    const float* W_ih   = (const float*)d_in[2];
    const float* W_hh   = (const float*)d_in[3];
    const float* b_ih   = (const float*)d_in[4];
    const float* b_hh   = (const float*)d_in[5];
    const float* W_out  = (const float*)d_in[6];
    const float* b_out  = (const float*)d_in[7];
    float* out = (float*)d_out;

    reset_flags<<<16, 256>>>();

    dim3 gA(H_ / 64, (B_ * T_) / 64);
    xw_kernel<<<gA, 256>>>(x, W_ih, b_ih, b_hh, out + HID_OFF);

    size_t smemB = (size_t)(48 * HRow) * sizeof(float);   // 208,896 B
    cudaFuncSetAttribute(rnn_recur, cudaFuncAttributeMaxDynamicSharedMemorySize,
                         (int)smemB);
    rnn_recur<<<NBLK, TB, smemB>>>(hidden, W_hh, out);

    out_kernel<<<(B_ * T_) / 64, 256>>>(out + HID_OFF, W_out, b_out, out + OUT_OFF);
}

// round 11
// speedup vs baseline: 1.0507x; 1.0507x over previous
#include <cuda_runtime.h>

// ---------------------------------------------------------------------------
// Elman RNN (relu), B=64, T=512, I=64, H=1024, O=64
// out = [ hidden_list (B,T,H) | output_list (B,T,O) | h_last (1,B,H) ]
// ---------------------------------------------------------------------------

#define B_   64
#define T_   512
#define I_   64
#define H_   1024
#define O_   64

#define HID_OFF  0
#define OUT_OFF  (B_ * T_ * H_)              // 33554432
#define HL_OFF   (OUT_OFF + B_ * T_ * O_)    // 35651584

#define NBLK 128        // persistent blocks (1/SM)
#define TB   256        // 2 warps / SMSP

// SMEM layout (floats): 32 K-chunks of 32 floats, padded to 36 (16B-aligned)
#define CH    36
#define HRow  1152      // 32 * 36

// scratch: h double buffer + per-(group,block) flags (128B stride)
__device__ __align__(16) float g_hbuf[2][B_ * H_];
__device__ unsigned g_flag[4][32][32];

typedef unsigned long long ull;
typedef ulonglong2 ull2;

__device__ __forceinline__ ull f2fma(ull a, ull b, ull c) {
    ull d;
    asm("fma.rn.f32x2 %0, %1, %2, %3;" : "=l"(d) : "l"(a), "l"(b), "l"(c));
    return d;
}
__device__ __forceinline__ float pairsum(ull a) {
    float lo = __uint_as_float((unsigned)(a & 0xffffffffull));
    float hi = __uint_as_float((unsigned)(a >> 32));
    return lo + hi;
}
__device__ __forceinline__ unsigned ld_acq(unsigned* p) {
    unsigned v;
    asm volatile("ld.acquire.gpu.u32 %0, [%1];" : "=r"(v) : "l"(p) : "memory");
    return v;
}
__device__ __forceinline__ void st_rel(unsigned* p, unsigned v) {
    asm volatile("st.release.gpu.u32 [%0], %1;" :: "l"(p), "r"(v) : "memory");
}

// ---------------------------------------------------------------------------
// Kernel A: xw[bt][h] = x[bt]·W_ih[h] + b_ih[h] + b_hh[h]  -> hidden region
// Block (0,0) also zeroes the flag array (replaces the reset launch).
// ---------------------------------------------------------------------------
__global__ void __launch_bounds__(256) xw_kernel(
    const float* __restrict__ x, const float* __restrict__ Wih,
    const float* __restrict__ bih, const float* __restrict__ bhh,
    float* __restrict__ hid_out)
{
    __shared__ float xs[64 * 65];
    __shared__ float ws[64 * 65];

    const int tid = threadIdx.x;
    const int hb  = blockIdx.x * 64;
    const int btb = blockIdx.y * 64;

    if (blockIdx.x == 0 && blockIdx.y == 0) {
        #pragma unroll
        for (int i = tid; i < 4 * 32 * 32; i += 256)
            ((unsigned*)g_flag)[i] = 0;
    }

    #pragma unroll
    for (int i = tid; i < 64 * 64; i += 256) {
        int r = i >> 6, c = i & 63;
        xs[r * 65 + c] = x[(btb + r) * 64 + c];
        ws[r * 65 + c] = Wih[(hb + r) * 64 + c];
    }
    __syncthreads();

    const int tx = tid & 15, ty = tid >> 4;
    float acc[4][4] = {};

    #pragma unroll 8
    for (int k = 0; k < 64; ++k) {
        float a0 = xs[(ty     ) * 65 + k];
        float a1 = xs[(ty + 16) * 65 + k];
        float a2 = xs[(ty + 32) * 65 + k];
        float a3 = xs[(ty + 48) * 65 + k];
        float b0 = ws[(tx     ) * 65 + k];
        float b1 = ws[(tx + 16) * 65 + k];
        float b2 = ws[(tx + 32) * 65 + k];
        float b3 = ws[(tx + 48) * 65 + k];
        acc[0][0] += a0 * b0; acc[0][1] += a0 * b1; acc[0][2] += a0 * b2; acc[0][3] += a0 * b3;
        acc[1][0] += a1 * b0; acc[1][1] += a1 * b1; acc[1][2] += a1 * b2; acc[1][3] += a1 * b3;
        acc[2][0] += a2 * b0; acc[2][1] += a2 * b1; acc[2][2] += a2 * b2; acc[2][3] += a2 * b3;
        acc[3][0] += a3 * b0; acc[3][1] += a3 * b1; acc[3][2] += a3 * b2; acc[3][3] += a3 * b3;
    }

    #pragma unroll
    for (int j = 0; j < 4; ++j) {
        int h = hb + tx + 16 * j;
        float bb = bih[h] + bhh[h];
        #pragma unroll
        for (int i = 0; i < 4; ++i) {
            int bt = btb + ty + 16 * i;
            hid_out[bt * H_ + h] = acc[i][j] + bb;
        }
    }
}

// ---------------------------------------------------------------------------
// Kernel B: persistent recurrence (R8 structure, LDS.128 operands).
// 128 blocks = 4 batch-groups(16 batches) x 32 col-groups(32 cols).
// kc = lane (K-chunk of 32), p = tid>>5 warp-uniform (pm batch octet,
// pn col octet). 8x8 f2fma tile with ull2 (LDS.128) loads -> butterfly
// shuffle reduction -> relu epilogue -> bar.arrive/sync -> flag release.
// All warps poll all 32 flags (lane -> flag); no post-poll block barrier.
// ---------------------------------------------------------------------------
__global__ void __launch_bounds__(TB, 1) rnn_recur(
    const float* __restrict__ hid_in,
    const float* __restrict__ Whh,
    float* __restrict__ out)
{
    extern __shared__ float sm[];
    float* wsm = sm;                 // 32 rows x HRow  (147,456 B)
    float* hsm = sm + 32 * HRow;     // 16 rows x HRow  (73,728 B)

    const int tid = threadIdx.x;
    const int bi  = blockIdx.x >> 5;
    const int ci  = blockIdx.x & 31;
    const int b0  = bi * 16;
    const int c0  = ci * 32;

    const int lane = tid & 31;
    const int kc   = lane;             // K-chunk (lane-spanning)
    const int p    = tid >> 5;         // warp-uniform tile position 0..7
    const int pm   = p & 1;
    const int pn   = p >> 1;

    // ---- stage W_hh slice once: rows c0..c0+31, chunked layout ----
    const float2* W2 = (const float2*)Whh;
    #pragma unroll 4
    for (int i = tid; i < 32 * 512; i += TB) {
        int r = i >> 9, q = i & 511;
        *(float2*)&wsm[r * HRow + (q >> 4) * CH + (q & 15) * 2] =
            __ldg(&W2[(c0 + r) * 512 + q]);
    }

    const float* hb_ = hsm + pm * 8 * HRow + kc * CH;
    const float* wb_ = wsm + pn * 8 * HRow + kc * CH;

    float* hid_out = out + HID_OFF;
    float* hlast   = out + HL_OFF;

    // epilogue mapping (post-shuffle): lane holds outputs 2*lane, 2*lane+1 of
    // the warp's 64 = (batch pm*8 + (lane>>2), cols pn*8 + 2*(lane&3) + {0,1})
    const int gb = b0 + pm * 8 + (lane >> 2);
    const int gc = c0 + pn * 8 + 2 * (lane & 3);

    #pragma unroll 1
    for (int s = 0; s < T_; ++s) {
        // prefetch xw for this thread's two outputs (own location, safe early)
        float2 xw = *(const float2*)&hid_out[((size_t)gb * T_ + s) * H_ + gc];

        // ---- wait: every warp polls all 32 producer flags (lane -> flag) ----
        if (s > 0) {
            while ((int)(ld_acq(&g_flag[bi][lane][0]) - (unsigned)s) < 0) { }
            __syncwarp();
        }

        // ---- stage h slice (16 x 1024): LDG.128 -> STS.128 ----
        const float4* hsrc = (s == 0) ? (const float4*)hid_in
                                      : (const float4*)g_hbuf[(s - 1) & 1];
        #pragma unroll
        for (int t = 0; t < 16; ++t) {
            int i  = t * 256 + tid;
            int r  = i >> 8, f4 = i & 255;
            float4 v = __ldcg(&hsrc[(b0 + r) * 256 + f4]);
            *(float4*)&hsm[r * HRow + (f4 >> 3) * CH + (f4 & 7) * 4] = v;
        }
        __syncthreads();

        // ---- 8x8 tile over private K-chunk of 32 (ull2 = LDS.128) ----
        ull acc[64];
        #pragma unroll
        for (int i = 0; i < 64; ++i) acc[i] = 0ull;

        #pragma unroll
        for (int k4 = 0; k4 < 8; ++k4) {
            ull2 hv[8];
            #pragma unroll
            for (int i = 0; i < 8; ++i)
                hv[i] = *(const ull2*)(hb_ + i * HRow + k4 * 4);
            ull2 wv[4];
            #pragma unroll
            for (int j = 0; j < 4; ++j)
                wv[j] = *(const ull2*)(wb_ + j * HRow + k4 * 4);
            #pragma unroll
            for (int i = 0; i < 8; ++i)
                #pragma unroll
                for (int j = 0; j < 4; ++j) {
                    acc[i * 8 + j] = f2fma(hv[i].x, wv[j].x, acc[i * 8 + j]);
                    acc[i * 8 + j] = f2fma(hv[i].y, wv[j].y, acc[i * 8 + j]);
                }
            #pragma unroll
            for (int j = 0; j < 4; ++j)
                wv[j] = *(const ull2*)(wb_ + (j + 4) * HRow + k4 * 4);
            #pragma unroll
            for (int i = 0; i < 8; ++i)
                #pragma unroll
                for (int j = 0; j < 4; ++j) {
                    acc[i * 8 + j + 4] = f2fma(hv[i].x, wv[j].x, acc[i * 8 + j + 4]);
                    acc[i * 8 + j + 4] = f2fma(hv[i].y, wv[j].y, acc[i * 8 + j + 4]);
                }
        }

        // ---- pairsum then 5-round butterfly shuffle reduction ----
        float vals[64];
        #pragma unroll
        for (int v = 0; v < 64; ++v) vals[v] = pairsum(acc[v]);

        #pragma unroll
        for (int m = 16, cnt = 32; m >= 1; m >>= 1, cnt >>= 1) {
            bool up = (lane & m) != 0;
            #pragma unroll
            for (int i = 0; i < 32; ++i) {
                if (i >= cnt) break;
                float send = up ? vals[i] : vals[i + cnt];
                float keep = up ? vals[i + cnt] : vals[i];
                float recv = __shfl_xor_sync(0xffffffffu, send, m);
                vals[i] = keep + recv;
            }
        }
        // lane now holds vals[0], vals[1] = outputs 2*lane, 2*lane+1

        float2 rr;
        rr.x = fmaxf(xw.x + vals[0], 0.0f);
        rr.y = fmaxf(xw.y + vals[1], 0.0f);

        *(float2*)&hid_out[((size_t)gb * T_ + s) * H_ + gc] = rr;
        *(float2*)&g_hbuf[s & 1][gb * H_ + gc] = rr;
        if (s == T_ - 1)
            *(float2*)&hlast[gb * H_ + gc] = rr;

        // ---- epilogue rendezvous: warps 1..7 arrive, warp 0 syncs+releases
        if (s != T_ - 1) {
            if (p == 0) {
                asm volatile("bar.sync 1, %0;" :: "n"(TB) : "memory");
                if (tid == 0)
                    st_rel(&g_flag[bi][ci][0], (unsigned)(s + 1));
            } else {
                asm volatile("bar.arrive 1, %0;" :: "n"(TB) : "memory");
            }
        }
    }
}

// ---------------------------------------------------------------------------
// Kernel C: output_list[bt][o] = hid[bt]·W_out[o] + b_out[o]   (f32x2)
// 64x64 tile, 256 threads, cp.async 16B double-buffered staging (depth 2).
// 32 K-chunks of 32 floats (FULL K=1024 — fixed from R10's 16-chunk bug).
// ---------------------------------------------------------------------------
#define OC 36           // chunk row stride (32 + 4 pad, 16B-aligned)

__device__ __forceinline__ void cp16(unsigned dst, const void* src) {
    asm volatile("cp.async.cg.shared.global [%0], [%1], 16;"
                 :: "r"(dst), "l"(src) : "memory");
}
__device__ __forceinline__ void cp_commit() {
    asm volatile("cp.async.commit_group;" ::: "memory");
}

__global__ void __launch_bounds__(256) out_kernel(
    const float* __restrict__ hid, const float* __restrict__ Wout,
    const float* __restrict__ bout, float* __restrict__ outp)
{
    __shared__ float hs[2][64 * OC];
    __shared__ float ws2[2][64 * OC];

    const int tid = threadIdx.x;
    const int btb = blockIdx.x * 64;
    const int tx = tid & 15, ty = tid >> 4;

    const float4* hid4  = (const float4*)hid;
    const float4* wout4 = (const float4*)Wout;

    const unsigned hs_base  = (unsigned)__cvta_generic_to_shared(&hs[0][0]);
    const unsigned ws_base  = (unsigned)__cvta_generic_to_shared(&ws2[0][0]);
    const unsigned buf_step = 64 * OC * 4;     // bytes per buffer

    // issue staging of K-chunk c (32 floats = 8 float4 per row) into buffer b
    auto issue = [&](int c, int b) {
        #pragma unroll
        for (int k = 0; k < 2; ++k) {
            int idx = k * 256 + tid;
            int r = idx >> 3, f = idx & 7;
            unsigned off = (unsigned)(r * OC + f * 4) * 4u + (unsigned)b * buf_step;
            cp16(hs_base + off, &hid4[(btb + r) * 256 + c * 8 + f]);
            cp16(ws_base + off, &wout4[r * 256 + c * 8 + f]);
        }
        cp_commit();
    };

    ull acc[4][4];
    #pragma unroll
    for (int i = 0; i < 4; ++i)
        #pragma unroll
        for (int j = 0; j < 4; ++j) acc[i][j] = 0ull;

    issue(0, 0);
    issue(1, 1);

    #pragma unroll 1
    for (int c = 0; c < 32; ++c) {              // FULL K: 32 chunks x 32 floats
        if (c < 31) asm volatile("cp.async.wait_group 1;" ::: "memory");
        else        asm volatile("cp.async.wait_group 0;" ::: "memory");
        __syncthreads();

        const int b = c & 1;
        const float* hb = &hs[b][0];
        const float* wb = &ws2[b][0];

        #pragma unroll
        for (int k4 = 0; k4 < 8; ++k4) {
            ull2 a2[4], b2[4];
            #pragma unroll
            for (int i = 0; i < 4; ++i)
                a2[i] = *(const ull2*)&hb[(ty + 16 * i) * OC + k4 * 4];
            #pragma unroll
            for (int j = 0; j < 4; ++j)
                b2[j] = *(const ull2*)&wb[(tx + 16 * j) * OC + k4 * 4];
            #pragma unroll
            for (int i = 0; i < 4; ++i)
                #pragma unroll
                for (int j = 0; j < 4; ++j) {
                    acc[i][j] = f2fma(a2[i].x, b2[j].x, acc[i][j]);
                    acc[i][j] = f2fma(a2[i].y, b2[j].y, acc[i][j]);
                }
        }
        __syncthreads();

        if (c < 30) issue(c + 2, b);
    }

    #pragma unroll
    for (int j = 0; j < 4; ++j) {
        int o = tx + 16 * j;
        float bb = bout[o];
        #pragma unroll
        for (int i = 0; i < 4; ++i)
            outp[(btb + ty + 16 * i) * O_ + o] = pairsum(acc[i][j]) + bb;
    }
}

// ---------------------------------------------------------------------------
extern "C" void kernel_launch(void* const* d_in, const int* in_sizes, int n_in,
                              void* d_out, int out_size) {
    const float* x      = (const float*)d_in[0];
    const float* hidden = (const float*)d_in[1];
    const float* W_ih   = (const float*)d_in[2];
    const float* W_hh   = (const float*)d_in[3];
    const float* b_ih   = (const float*)d_in[4];
    const float* b_hh   = (const float*)d_in[5];
    const float* W_out  = (const float*)d_in[6];
    const float* b_out  = (const float*)d_in[7];
    float* out = (float*)d_out;

    dim3 gA(H_ / 64, (B_ * T_) / 64);
    xw_kernel<<<gA, 256>>>(x, W_ih, b_ih, b_hh, out + HID_OFF);

    size_t smemB = (size_t)(48 * HRow) * sizeof(float);   // 221,184 B
    cudaFuncSetAttribute(rnn_recur, cudaFuncAttributeMaxDynamicSharedMemorySize,
                         (int)smemB);
    rnn_recur<<<NBLK, TB, smemB>>>(hidden, W_hh, out);

    out_kernel<<<(B_ * T_) / 64, 256>>>(out + HID_OFF, W_out, b_out, out + OUT_OFF);
}

// round 13
// speedup vs baseline: 1.1811x; 1.1242x over previous
#include <cuda_runtime.h>

// ---------------------------------------------------------------------------
// Elman RNN (relu), B=64, T=512, I=64, H=1024, O=64
// out = [ hidden_list (B,T,H) | output_list (B,T,O) | h_last (1,B,H) ]
// ---------------------------------------------------------------------------

#define B_   64
#define T_   512
#define I_   64
#define H_   1024
#define O_   64

#define HID_OFF  0
#define OUT_OFF  (B_ * T_ * H_)              // 33554432
#define HL_OFF   (OUT_OFF + B_ * T_ * O_)    // 35651584

#define NBLK 128        // persistent blocks (1/SM)
#define TB   256        // 2 warps / SMSP

// SMEM layout (floats): 32 K-chunks of 32 floats, each padded to 34
#define CH    34
#define HRow  1088      // 32 * 34

// scratch: h double buffer + per-(group,block) flags (128B stride)
__device__ __align__(16) float g_hbuf[2][B_ * H_];
__device__ unsigned g_flag[4][32][32];

typedef unsigned long long ull;

__device__ __forceinline__ ull f2fma(ull a, ull b, ull c) {
    ull d;
    asm("fma.rn.f32x2 %0, %1, %2, %3;" : "=l"(d) : "l"(a), "l"(b), "l"(c));
    return d;
}
__device__ __forceinline__ float pairsum(ull a) {
    float lo = __uint_as_float((unsigned)(a & 0xffffffffull));
    float hi = __uint_as_float((unsigned)(a >> 32));
    return lo + hi;
}
__device__ __forceinline__ unsigned ld_acq(unsigned* p) {
    unsigned v;
    asm volatile("ld.acquire.gpu.u32 %0, [%1];" : "=r"(v) : "l"(p) : "memory");
    return v;
}
__device__ __forceinline__ void st_rel(unsigned* p, unsigned v) {
    asm volatile("st.release.gpu.u32 [%0], %1;" :: "l"(p), "r"(v) : "memory");
}

// ---------------------------------------------------------------------------
// Kernel A: xw[bt][h] = x[bt]·W_ih[h] + b_ih[h] + b_hh[h]  -> hidden region
// f32x2 version (pad 66 so k-pairs are 8B-aligned). Block (0,0) zeroes flags.
// ---------------------------------------------------------------------------
__global__ void __launch_bounds__(256) xw_kernel(
    const float* __restrict__ x, const float* __restrict__ Wih,
    const float* __restrict__ bih, const float* __restrict__ bhh,
    float* __restrict__ hid_out)
{
    __shared__ float xs[64 * 66];
    __shared__ float ws[64 * 66];

    const int tid = threadIdx.x;
    const int hb  = blockIdx.x * 64;
    const int btb = blockIdx.y * 64;

    if (blockIdx.x == 0 && blockIdx.y == 0) {
        #pragma unroll
        for (int i = tid; i < 4 * 32 * 32; i += 256)
            ((unsigned*)g_flag)[i] = 0;
    }

    const float2* x2 = (const float2*)x;
    const float2* w2 = (const float2*)Wih;
    #pragma unroll
    for (int i = tid; i < 64 * 32; i += 256) {
        int r = i >> 5, q = i & 31;
        *(float2*)&xs[r * 66 + 2 * q] = x2[(btb + r) * 32 + q];
        *(float2*)&ws[r * 66 + 2 * q] = w2[(hb + r) * 32 + q];
    }
    __syncthreads();

    const int tx = tid & 15, ty = tid >> 4;
    ull acc[4][4];
    #pragma unroll
    for (int i = 0; i < 4; ++i)
        #pragma unroll
        for (int j = 0; j < 4; ++j) acc[i][j] = 0ull;

    #pragma unroll 8
    for (int k2 = 0; k2 < 32; ++k2) {
        ull a[4], b[4];
        #pragma unroll
        for (int i = 0; i < 4; ++i)
            a[i] = *(const ull*)&xs[(ty + 16 * i) * 66 + 2 * k2];
        #pragma unroll
        for (int j = 0; j < 4; ++j)
            b[j] = *(const ull*)&ws[(tx + 16 * j) * 66 + 2 * k2];
        #pragma unroll
        for (int i = 0; i < 4; ++i)
            #pragma unroll
            for (int j = 0; j < 4; ++j)
                acc[i][j] = f2fma(a[i], b[j], acc[i][j]);
    }

    #pragma unroll
    for (int j = 0; j < 4; ++j) {
        int h = hb + tx + 16 * j;
        float bb = bih[h] + bhh[h];
        #pragma unroll
        for (int i = 0; i < 4; ++i) {
            int bt = btb + ty + 16 * i;
            hid_out[bt * H_ + h] = pairsum(acc[i][j]) + bb;
        }
    }
}

// ---------------------------------------------------------------------------
// Kernel B: persistent recurrence (R8 GEMM/reduction; per-warp staging).
// 128 blocks = 4 batch-groups(16 batches) x 32 col-groups(32 cols).
// Warp p polls only producers {4p..4p+3} (lanes 0-3, parallel) PLUS own
// block's flag (lane 4 — guarantees all local warps passed step s-1's bar,
// so hsm restaging cannot race prior FMA reads). It then stages only its
// own 4 K-chunks (16 LDG.128 -> 2x STS.64 each; CH=34 keeps the layout
// 8B-aligned and conflict-free). __syncthreads joins; then R8's 8x8 f2fma
// tile (kc = lane), butterfly shuffle reduction, relu epilogue,
// bar.arrive/sync, st.release flag.
// ---------------------------------------------------------------------------
__global__ void __launch_bounds__(TB, 1) rnn_recur(
    const float* __restrict__ hid_in,
    const float* __restrict__ Whh,
    float* __restrict__ out)
{
    extern __shared__ float sm[];
    float* wsm = sm;                 // 32 rows x HRow  (~136 KB)
    float* hsm = sm + 32 * HRow;     // 16 rows x HRow  (~68 KB)

    const int tid = threadIdx.x;
    const int bi  = blockIdx.x >> 5;
    const int ci  = blockIdx.x & 31;
    const int b0  = bi * 16;
    const int c0  = ci * 32;

    const int lane = tid & 31;
    const int kc   = lane;             // K-chunk (lane-spanning)
    const int p    = tid >> 5;         // warp-uniform tile position 0..7
    const int pm   = p & 1;
    const int pn   = p >> 1;

    // ---- stage W_hh slice once: rows c0..c0+31, chunked layout ----
    const float2* W2 = (const float2*)Whh;
    #pragma unroll 4
    for (int i = tid; i < 32 * 512; i += TB) {
        int r = i >> 9, q = i & 511;
        *(float2*)&wsm[r * HRow + (q >> 4) * CH + (q & 15) * 2] =
            __ldg(&W2[(c0 + r) * 512 + q]);
    }

    const float* hb_ = hsm + pm * 8 * HRow + kc * CH;
    const float* wb_ = wsm + pn * 8 * HRow + kc * CH;

    float* hid_out = out + HID_OFF;
    float* hlast   = out + HL_OFF;

    // epilogue mapping (post-shuffle): lane holds outputs 2*lane, 2*lane+1 of
    // the warp's 64 = (batch pm*8 + (lane>>2), cols pn*8 + 2*(lane&3) + {0,1})
    const int gb = b0 + pm * 8 + (lane >> 2);
    const int gc = c0 + pn * 8 + 2 * (lane & 3);

    // staging: warp p owns chunks 4p..4p+3; lane -> (cc = lane>>3, f4 = lane&7)
    const int st_cc = lane >> 3;       // chunk within quad
    const int st_f4 = lane & 7;

    #pragma unroll 1
    for (int s = 0; s < T_; ++s) {
        // prefetch xw for this thread's two outputs (own location, safe early)
        float2 xw = *(const float2*)&hid_out[((size_t)gb * T_ + s) * H_ + gc];

        // ---- per-warp parallel poll: producers 4p..4p+3 + own flag ----
        if (s > 0) {
            if (lane < 4) {
                unsigned* fp = &g_flag[bi][4 * p + lane][0];
                while ((int)(ld_acq(fp) - (unsigned)s) < 0) { }
            } else if (lane == 4) {
                unsigned* fp = &g_flag[bi][ci][0];
                while ((int)(ld_acq(fp) - (unsigned)s) < 0) { }
            }
            __syncwarp();
        }

        // ---- stage own 4 chunks: row t, chunks 4p..4p+3 (512B spans) ----
        // LDG.128 then two STS.64 (chunk base 136B not 16B-aligned; 8B is)
        const float4* hsrc = (s == 0) ? (const float4*)hid_in
                                      : (const float4*)g_hbuf[(s - 1) & 1];
        #pragma unroll
        for (int t = 0; t < 16; ++t) {
            float4 v = __ldcg(&hsrc[(b0 + t) * 256 + (4 * p + st_cc) * 8 + st_f4]);
            float* dst = &hsm[t * HRow + (4 * p + st_cc) * CH + st_f4 * 4];
            *(float2*)dst       = make_float2(v.x, v.y);
            *(float2*)(dst + 2) = make_float2(v.z, v.w);
        }
        __syncthreads();

        // ---- 8x8 tile over private K-chunk of 32 (R8 exact) ----
        ull acc[64];
        #pragma unroll
        for (int i = 0; i < 64; ++i) acc[i] = 0ull;

        #pragma unroll
        for (int k2 = 0; k2 < 16; ++k2) {
            ull hv[8];
            #pragma unroll
            for (int i = 0; i < 8; ++i)
                hv[i] = *(const ull*)(hb_ + i * HRow + k2 * 2);
            ull wv[4];
            #pragma unroll
            for (int j = 0; j < 4; ++j)
                wv[j] = *(const ull*)(wb_ + j * HRow + k2 * 2);
            #pragma unroll
            for (int i = 0; i < 8; ++i)
                #pragma unroll
                for (int j = 0; j < 4; ++j)
                    acc[i * 8 + j] = f2fma(hv[i], wv[j], acc[i * 8 + j]);
            #pragma unroll
            for (int j = 0; j < 4; ++j)
                wv[j] = *(const ull*)(wb_ + (j + 4) * HRow + k2 * 2);
            #pragma unroll
            for (int i = 0; i < 8; ++i)
                #pragma unroll
                for (int j = 0; j < 4; ++j)
                    acc[i * 8 + j + 4] = f2fma(hv[i], wv[j], acc[i * 8 + j + 4]);
        }

        // ---- pairsum then 5-round butterfly shuffle reduction ----
        float vals[64];
        #pragma unroll
        for (int v = 0; v < 64; ++v) vals[v] = pairsum(acc[v]);

        #pragma unroll
        for (int m = 16, cnt = 32; m >= 1; m >>= 1, cnt >>= 1) {
            bool up = (lane & m) != 0;
            #pragma unroll
            for (int i = 0; i < 32; ++i) {
                if (i >= cnt) break;
                float send = up ? vals[i] : vals[i + cnt];
                float keep = up ? vals[i + cnt] : vals[i];
                float recv = __shfl_xor_sync(0xffffffffu, send, m);
                vals[i] = keep + recv;
            }
        }
        // lane now holds vals[0], vals[1] = outputs 2*lane, 2*lane+1

        float2 rr;
        rr.x = fmaxf(xw.x + vals[0], 0.0f);
        rr.y = fmaxf(xw.y + vals[1], 0.0f);

        *(float2*)&hid_out[((size_t)gb * T_ + s) * H_ + gc] = rr;
        *(float2*)&g_hbuf[s & 1][gb * H_ + gc] = rr;
        if (s == T_ - 1)
            *(float2*)&hlast[gb * H_ + gc] = rr;

        // ---- epilogue rendezvous: warps 1..7 arrive, warp 0 syncs+releases
        if (s != T_ - 1) {
            if (p == 0) {
                asm volatile("bar.sync 1, %0;" :: "n"(TB) : "memory");
                if (tid == 0)
                    st_rel(&g_flag[bi][ci][0], (unsigned)(s + 1));
            } else {
                asm volatile("bar.arrive 1, %0;" :: "n"(TB) : "memory");
            }
        }
    }
}

// ---------------------------------------------------------------------------
// Kernel C: output_list[bt][o] = hid[bt]·W_out[o] + b_out[o]   (f32x2)
// 64x64 tile, 256 threads, cp.async double-buffered, FULL K (32 chunks).
// ---------------------------------------------------------------------------
#define OC 36           // chunk row stride (32 + 4 pad, 16B-aligned)

typedef ulonglong2 ull2;

__device__ __forceinline__ void cp16(unsigned dst, const void* src) {
    asm volatile("cp.async.cg.shared.global [%0], [%1], 16;"
                 :: "r"(dst), "l"(src) : "memory");
}
__device__ __forceinline__ void cp_commit() {
    asm volatile("cp.async.commit_group;" ::: "memory");
}

__global__ void __launch_bounds__(256) out_kernel(
    const float* __restrict__ hid, const float* __restrict__ Wout,
    const float* __restrict__ bout, float* __restrict__ outp)
{
    __shared__ float hs[2][64 * OC];
    __shared__ float ws2[2][64 * OC];

    const int tid = threadIdx.x;
    const int btb = blockIdx.x * 64;
    const int tx = tid & 15, ty = tid >> 4;

    const float4* hid4  = (const float4*)hid;
    const float4* wout4 = (const float4*)Wout;

    const unsigned hs_base  = (unsigned)__cvta_generic_to_shared(&hs[0][0]);
    const unsigned ws_base  = (unsigned)__cvta_generic_to_shared(&ws2[0][0]);
    const unsigned buf_step = 64 * OC * 4;     // bytes per buffer

    auto issue = [&](int c, int b) {
        #pragma unroll
        for (int k = 0; k < 2; ++k) {
            int idx = k * 256 + tid;
            int r = idx >> 3, f = idx & 7;
            unsigned off = (unsigned)(r * OC + f * 4) * 4u + (unsigned)b * buf_step;
            cp16(hs_base + off, &hid4[(btb + r) * 256 + c * 8 + f]);
            cp16(ws_base + off, &wout4[r * 256 + c * 8 + f]);
        }
        cp_commit();
    };

    ull acc[4][4];
    #pragma unroll
    for (int i = 0; i < 4; ++i)
        #pragma unroll
        for (int j = 0; j < 4; ++j) acc[i][j] = 0ull;

    issue(0, 0);
    issue(1, 1);

    #pragma unroll 1
    for (int c = 0; c < 32; ++c) {              // FULL K: 32 chunks x 32 floats
        if (c < 31) asm volatile("cp.async.wait_group 1;" ::: "memory");
        else        asm volatile("cp.async.wait_group 0;" ::: "memory");
        __syncthreads();

        const int b = c & 1;
        const float* hb = &hs[b][0];
        const float* wb = &ws2[b][0];

        #pragma unroll
        for (int k4 = 0; k4 < 8; ++k4) {
            ull2 a2[4], b2[4];
            #pragma unroll
            for (int i = 0; i < 4; ++i)
                a2[i] = *(const ull2*)&hb[(ty + 16 * i) * OC + k4 * 4];
            #pragma unroll
            for (int j = 0; j < 4; ++j)
                b2[j] = *(const ull2*)&wb[(tx + 16 * j) * OC + k4 * 4];
            #pragma unroll
            for (int i = 0; i < 4; ++i)
                #pragma unroll
                for (int j = 0; j < 4; ++j) {
                    acc[i][j] = f2fma(a2[i].x, b2[j].x, acc[i][j]);
                    acc[i][j] = f2fma(a2[i].y, b2[j].y, acc[i][j]);
                }
        }
        __syncthreads();

        if (c < 30) issue(c + 2, b);
    }

    #pragma unroll
    for (int j = 0; j < 4; ++j) {
        int o = tx + 16 * j;
        float bb = bout[o];
        #pragma unroll
        for (int i = 0; i < 4; ++i)
            outp[(btb + ty + 16 * i) * O_ + o] = pairsum(acc[i][j]) + bb;
    }
}

// ---------------------------------------------------------------------------
extern "C" void kernel_launch(void* const* d_in, const int* in_sizes, int n_in,
                              void* d_out, int out_size) {
    const float* x      = (const float*)d_in[0];
    const float* hidden = (const float*)d_in[1];
    const float* W_ih   = (const float*)d_in[2];
    const float* W_hh   = (const float*)d_in[3];
    const float* b_ih   = (const float*)d_in[4];
    const float* b_hh   = (const float*)d_in[5];
    const float* W_out  = (const float*)d_in[6];
    const float* b_out  = (const float*)d_in[7];
    float* out = (float*)d_out;

    dim3 gA(H_ / 64, (B_ * T_) / 64);
    xw_kernel<<<gA, 256>>>(x, W_ih, b_ih, b_hh, out + HID_OFF);

    size_t smemB = (size_t)(48 * HRow) * sizeof(float);   // 208,896 B
    cudaFuncSetAttribute(rnn_recur, cudaFuncAttributeMaxDynamicSharedMemorySize,
                         (int)smemB);
    rnn_recur<<<NBLK, TB, smemB>>>(hidden, W_hh, out);

    out_kernel<<<(B_ * T_) / 64, 256>>>(out + HID_OFF, W_out, b_out, out + OUT_OFF);
}